// round 11
// baseline (speedup 1.0000x reference)
#include <cuda_runtime.h>
#include <cuda_fp16.h>
#include <stdint.h>

// Problem constants
#define BB 4
#define NN 512
#define MM 4096
#define DD 256
#define HH 8
#define C2EXP 0.25505551190558915f   // (1/sqrt(32)) * log2(e)

// ---------------------------------------------------------------------------
// Scratch (static device globals)
// ---------------------------------------------------------------------------
__device__ __half g_amr_h [BB*NN*DD];
__device__ __half g_vis_h [BB*MM*DD];
__device__ __half g_Wt    [6*DD*DD];          // transposed weights [n][k] f16
__device__ __half g_amr_qk[BB*NN*DD];
__device__ __half g_amr_v [BB*NN*DD];
__device__ __half g_vis_qk[BB*MM*DD];
__device__ __half g_vis_v [BB*MM*DD];
__device__ __half g_amr_att[BB*NN*DD];
__device__ __half g_vis_att[BB*MM*DD];
__device__ float  g_po[2*BB*NN*DD];           // dir1 split partial O
__device__ float  g_pl[2*BB*HH*NN];           // dir1 split partial l

// ---------------------------------------------------------------------------
// Helpers
// ---------------------------------------------------------------------------
__device__ __forceinline__ void mma_f16(float c[4],
                                        uint32_t a0, uint32_t a1,
                                        uint32_t a2, uint32_t a3,
                                        uint32_t b0, uint32_t b1) {
    asm volatile(
        "mma.sync.aligned.m16n8k16.row.col.f32.f16.f16.f32 "
        "{%0,%1,%2,%3}, {%4,%5,%6,%7}, {%8,%9}, {%0,%1,%2,%3};"
        : "+f"(c[0]), "+f"(c[1]), "+f"(c[2]), "+f"(c[3])
        : "r"(a0), "r"(a1), "r"(a2), "r"(a3), "r"(b0), "r"(b1));
}

__device__ __forceinline__ uint32_t smem_u32(const void* p) {
    return (uint32_t)__cvta_generic_to_shared(p);
}

#define CP16(dst_u32, src) \
    asm volatile("cp.async.ca.shared.global [%0], [%1], 16;" \
                 :: "r"(dst_u32), "l"(src))
#define CP_COMMIT() asm volatile("cp.async.commit_group;")
#define CP_WAIT(n)  asm volatile("cp.async.wait_group %0;" :: "n"(n))

#define LDM4(r0, r1, r2, r3, addr) \
    asm volatile("ldmatrix.sync.aligned.m8n8.x4.shared.b16 {%0,%1,%2,%3}, [%4];" \
                 : "=r"(r0), "=r"(r1), "=r"(r2), "=r"(r3) : "r"(addr))
#define LDM4T(r0, r1, r2, r3, addr) \
    asm volatile("ldmatrix.sync.aligned.m8n8.x4.trans.shared.b16 {%0,%1,%2,%3}, [%4];" \
                 : "=r"(r0), "=r"(r1), "=r"(r2), "=r"(r3) : "r"(addr))

__device__ __forceinline__ uint32_t pack_h2(float a, float b) {
    uint32_t r;
    asm("cvt.rn.f16x2.f32 %0, %1, %2;" : "=r"(r) : "f"(b), "f"(a));
    return r;
}
__device__ __forceinline__ uint32_t ex2_h2(uint32_t x) {
    uint32_t r;
    asm("ex2.approx.f16x2 %0, %1;" : "=r"(r) : "r"(x));
    return r;
}

// ---------------------------------------------------------------------------
// Merged prep: [0,4608) fp32->fp16 features; [4608,4992) weight transpose.
// 256 threads.
// ---------------------------------------------------------------------------
__global__ void prep_all(const float* __restrict__ amr, const float* __restrict__ vis,
                         const float* W0, const float* W1, const float* W2,
                         const float* W3, const float* W4, const float* W5,
                         __half* __restrict__ amr_h, __half* __restrict__ vis_h,
                         __half* __restrict__ Wt)
{
    __shared__ float tile[32][33];
    const int idb = blockIdx.x;
    const int tid = threadIdx.x;

    if (idb < 4608) {
        int i4 = (idb * 256 + tid) * 4;
        const int na = BB * NN * DD;
        const float* src; __half* dst;
        if (i4 < na) { src = amr; dst = amr_h; }
        else {
            i4 -= na;
            if (i4 >= BB * MM * DD) return;
            src = vis; dst = vis_h;
        }
        const float4 v = *(const float4*)&src[i4];
        *(half2*)&dst[i4]     = __floats2half2_rn(v.x, v.y);
        *(half2*)&dst[i4 + 2] = __floats2half2_rn(v.z, v.w);
    } else {
        const int z  = idb - 4608;           // 0..383
        const int mi = z >> 6;               // matrix 0..5
        const int bx = z & 7;                // n tile
        const int by = (z >> 3) & 7;         // k tile
        const float* Ws[6] = {W0, W1, W2, W3, W4, W5};
        const float* in = Ws[mi];
        __half* out = Wt + (size_t)mi * DD * DD;
        const int x0 = bx * 32, y0 = by * 32;
        const int tx = tid & 31, ty = tid >> 5;   // 32 x 8
        #pragma unroll
        for (int j = 0; j < 32; j += 8)
            tile[ty + j][tx] = in[(size_t)(y0 + ty + j) * DD + x0 + tx];
        __syncthreads();
        #pragma unroll
        for (int j = 0; j < 32; j += 8)
            out[(size_t)(x0 + ty + j) * DD + y0 + tx] = __float2half(tile[tx][ty + j]);
    }
}

// ---------------------------------------------------------------------------
// fp16 GEMM body: C[64x64] = A[S,256] @ Wt[n][k]^T  (unchanged)
// ---------------------------------------------------------------------------
template <bool EPI>
__device__ __forceinline__ void gemm_body(const __half* __restrict__ A,
                                          const __half* __restrict__ W,
                                          const float* __restrict__ bias,
                                          const float* __restrict__ Xm,
                                          __half* __restrict__ Ch,
                                          float* __restrict__ Cf,
                                          int row0, int col0)
{
    __shared__ __half Ab[2][64][72];
    __shared__ __half Wb[2][64][72];

    const int tid  = threadIdx.x;
    const int w    = tid >> 5;
    const int lane = tid & 31;
    const int g    = lane >> 2;
    const int t    = lane & 3;
    const int m    = lane >> 3;
    const int r    = lane & 7;
    const int sr   = tid >> 1;
    const int scb  = (tid & 1) * 32;

    const uint32_t abase = smem_u32(&Ab[0][0][0]);
    const uint32_t wbase = smem_u32(&Wb[0][0][0]);
    const uint32_t BUF = 64 * 72 * 2;
    const uint32_t a_l = (uint32_t)(((m & 1) * 8 + r) * 144 + (m >> 1) * 16);
    const uint32_t w_l = (uint32_t)(((m >> 1) * 8 + r) * 144 + (m & 1) * 16);

    float acc[8][4];
    #pragma unroll
    for (int nt = 0; nt < 8; nt++)
        #pragma unroll
        for (int i = 0; i < 4; i++) acc[nt][i] = 0.0f;

    auto stage = [&](int s, int kc) {
        const __half* ap = &A[(size_t)(row0 + sr) * 256 + kc + scb];
        const __half* wp = &W[(size_t)(col0 + sr) * 256 + kc + scb];
        #pragma unroll
        for (int o = 0; o < 32; o += 8) {
            CP16(smem_u32(&Ab[s][sr][scb + o]), ap + o);
            CP16(smem_u32(&Wb[s][sr][scb + o]), wp + o);
        }
    };

    stage(0, 0); CP_COMMIT();

    for (int c = 0; c < 4; c++) {
        if (c < 3) { stage((c + 1) & 1, (c + 1) * 64); CP_COMMIT(); CP_WAIT(1); }
        else       { CP_WAIT(0); }
        __syncthreads();
        const int s = c & 1;
        const uint32_t ab = abase + s * BUF + w * 2304 + a_l;
        const uint32_t wb = wbase + s * BUF + w_l;
        #pragma unroll
        for (int kk = 0; kk < 4; kk++) {
            uint32_t a0, a1, a2, a3;
            LDM4(a0, a1, a2, a3, ab + kk * 32);
            #pragma unroll
            for (int j = 0; j < 4; j++) {
                uint32_t b00, b01, b10, b11;
                LDM4(b00, b01, b10, b11, wb + j * 2304 + kk * 32);
                mma_f16(acc[2 * j],     a0, a1, a2, a3, b00, b01);
                mma_f16(acc[2 * j + 1], a0, a1, a2, a3, b10, b11);
            }
        }
        __syncthreads();
    }

    const size_t r_lo = (size_t)(row0 + 16 * w + g);
    const size_t r_hi = r_lo + 8;
    #pragma unroll
    for (int nt = 0; nt < 8; nt++) {
        const int col = col0 + nt * 8 + 2 * t;
        if (EPI) {
            const float2 bv  = *(const float2*)&bias[col];
            const float2 xlo = *(const float2*)&Xm[r_lo * 256 + col];
            const float2 xhi = *(const float2*)&Xm[r_hi * 256 + col];
            float2 lo, hi;
            lo.x = (acc[nt][0] + bv.x) * xlo.x; lo.y = (acc[nt][1] + bv.y) * xlo.y;
            hi.x = (acc[nt][2] + bv.x) * xhi.x; hi.y = (acc[nt][3] + bv.y) * xhi.y;
            *(float2*)&Cf[r_lo * 256 + col] = lo;
            *(float2*)&Cf[r_hi * 256 + col] = hi;
        } else {
            *(half2*)&Ch[r_lo * 256 + col] = __floats2half2_rn(acc[nt][0], acc[nt][1]);
            *(half2*)&Ch[r_hi * 256 + col] = __floats2half2_rn(acc[nt][2], acc[nt][3]);
        }
    }
}

__global__ void __launch_bounds__(128) proj_all(const __half* amr_h, const __half* vis_h,
                                                const __half* Wt,
                                                __half* amr_qk, __half* amr_v,
                                                __half* vis_qk, __half* vis_v)
{
    const int y = blockIdx.y;
    const int col0 = blockIdx.x * 64;
    const __half *A, *W; __half* C; int row0;
    if      (y < 32)  { A = amr_h; W = Wt + 0 * DD * DD; C = amr_qk; row0 = y * 64; }
    else if (y < 64)  { A = amr_h; W = Wt + 1 * DD * DD; C = amr_v;  row0 = (y - 32) * 64; }
    else if (y < 320) { A = vis_h; W = Wt + 2 * DD * DD; C = vis_qk; row0 = (y - 64) * 64; }
    else              { A = vis_h; W = Wt + 3 * DD * DD; C = vis_v;  row0 = (y - 320) * 64; }
    gemm_body<false>(A, W, nullptr, nullptr, C, nullptr, row0, col0);
}

__global__ void __launch_bounds__(128) epi_all(const __half* amr_att, const __half* vis_att,
                                               const __half* Wt,
                                               const float* b_amr, const float* b_vis,
                                               const float* amr_f, const float* vis_f,
                                               float* out_amr, float* out_vis)
{
    const int y = blockIdx.y;
    const int col0 = blockIdx.x * 64;
    const __half *A, *W; const float *bias, *Xm; float* C; int row0;
    if (y < 32) { A = amr_att; W = Wt + 4 * DD * DD; bias = b_amr; Xm = amr_f;
                  C = out_amr; row0 = y * 64; }
    else        { A = vis_att; W = Wt + 5 * DD * DD; bias = b_vis; Xm = vis_f;
                  C = out_vis; row0 = (y - 32) * 64; }
    gemm_body<true>(A, W, bias, Xm, nullptr, C, row0, col0);
}

// ---------------------------------------------------------------------------
// Fused attention — key-split warps, 32-QUERY tiles (occupancy restore).
// Warp w owns keys [16w,16w+16) of each 64-key chunk, ALL 32 queries.
// Persistent regs: qa 16, of 32, lf 8. launch_bounds(128,4) -> 4 CTAs/SM.
// Grid 5120 1D: [0,1024) dir1 (split-KV x2, unnorm partials), [1024,5120) dir2.
// ---------------------------------------------------------------------------
__global__ void __launch_bounds__(128, 4) attn_all(
    const __half* __restrict__ amr_qk, const __half* __restrict__ amr_v,
    const __half* __restrict__ vis_qk, const __half* __restrict__ vis_v,
    __half* __restrict__ vis_att, float* __restrict__ po, float* __restrict__ pl,
    const int* __restrict__ pad_mask)
{
    // main phase: Qs[32][40]h @0 (2560) | Kb[2][64][40]h @2560 (10240)
    //             Vb[2][64][40]h @12800 (10240) | Msk[2][64]i @23040 (512)
    // reduce phase overlay: red[4][32][36]f @0 (18432) | lred[4][32]f @18432
    __shared__ __align__(16) char SM[23552];
    int*   Msk = reinterpret_cast<int*>(SM + 23040);
    float (*red)[32][36] = reinterpret_cast<float(*)[32][36]>(SM);
    float (*lred)[32]    = reinterpret_cast<float(*)[32]>(SM + 18432);

    const uint32_t qbase = smem_u32(SM);
    const uint32_t kbase = smem_u32(SM + 2560);
    const uint32_t vbase = smem_u32(SM + 12800);
    const uint32_t KBUF = 64 * 40 * 2;              // 5120

    // --- decode block role ---
    const __half *Qp, *Kp, *Vp;
    int Lq, LkT, kv0, nch, b, h, q0, norm;
    const int* mask;
    float* Opf = nullptr; float* Lp = nullptr; __half* Oph = nullptr;
    {
        const int id = blockIdx.x;
        if (id < 1024) {
            b = id & 3; h = (id >> 2) & 7; q0 = ((id >> 5) & 15) * 32;
            const int sp = id >> 9;
            Qp = amr_qk; Kp = vis_qk; Vp = vis_v;
            Lq = NN; LkT = MM; kv0 = sp * (MM / 2); nch = (MM / 2) / 64;
            mask = nullptr; norm = 0;
            Opf = po + (size_t)sp * BB * NN * DD;
            Lp  = pl + sp * BB * HH * NN;
        } else {
            const int j = id - 1024;
            b = j & 3; h = (j >> 2) & 7; q0 = (j >> 5) * 32;
            Qp = vis_qk; Kp = amr_qk; Vp = amr_v;
            Lq = MM; LkT = NN; kv0 = 0; nch = NN / 64;
            mask = pad_mask; norm = 1;
            Oph = vis_att;
        }
    }

    const int tid  = threadIdx.x;
    const int w    = tid >> 5;
    const int lane = tid & 31;
    const int g    = lane >> 2;
    const int t    = lane & 3;
    const int m    = lane >> 3;
    const int r    = lane & 7;
    const int sr   = tid >> 1;           // KV staging row 0..63
    const int scb  = (tid & 1) * 16;     // KV staging col (halves)
    const int srq  = tid >> 2;           // Q staging row 0..31
    const int scq  = (tid & 3) * 8;      // Q staging col (halves)

    const uint32_t q_l = (uint32_t)(((m & 1) * 8 + r) * 80 + (m >> 1) * 16);
    const uint32_t k_l = (uint32_t)(((m >> 1) * 8 + r) * 80 + (m & 1) * 16);
    const uint32_t v_l = (uint32_t)(r * 80 + m * 16);
    const uint32_t onesb = (g == 0) ? 0x3C003C00u : 0u;   // B col 0 = ones

    __half (*QsW)[40]     = reinterpret_cast<__half(*)[40]>(SM);
    __half (*KbW)[64][40] = reinterpret_cast<__half(*)[64][40]>(SM + 2560);
    __half (*VbW)[64][40] = reinterpret_cast<__half(*)[64][40]>(SM + 12800);

    auto stageKV = [&](int s, int kc) {
        const size_t base = ((size_t)b * LkT + kv0 + kc + sr) * 256 + h * 32 + scb;
        CP16(smem_u32(&KbW[s][sr][scb]),     &Kp[base]);
        CP16(smem_u32(&KbW[s][sr][scb + 8]), &Kp[base + 8]);
        CP16(smem_u32(&VbW[s][sr][scb]),     &Vp[base]);
        CP16(smem_u32(&VbW[s][sr][scb + 8]), &Vp[base + 8]);
        if (mask && tid < 16)
            CP16(smem_u32(&Msk[s * 64 + tid * 4]), &mask[b * LkT + kv0 + kc + tid * 4]);
    };

    // Stage Q (32 rows x 32 halves; one CP16 per thread) + first KV chunk
    {
        const size_t qb = ((size_t)b * Lq + q0 + srq) * 256 + h * 32 + scq;
        CP16(smem_u32(&QsW[srq][scq]), &Qp[qb]);
    }
    stageKV(0, 0);
    CP_COMMIT();

    uint32_t qa[2][2][4];          // [m-tile][kk][frag]
    float of[2][4][4];             // [m-tile][n-tile][frag] partial O
    float lf[2][4];                // [m-tile][frag]        partial l
    #pragma unroll
    for (int mt = 0; mt < 2; mt++) {
        #pragma unroll
        for (int nt = 0; nt < 4; nt++)
            #pragma unroll
            for (int i = 0; i < 4; i++) of[mt][nt][i] = 0.0f;
        #pragma unroll
        for (int i = 0; i < 4; i++) lf[mt][i] = 0.0f;
    }

    for (int c = 0; c < nch; c++) {
        if (c + 1 < nch) { stageKV((c + 1) & 1, (c + 1) * 64); CP_COMMIT(); CP_WAIT(1); }
        else             { CP_WAIT(0); }
        __syncthreads();
        const int s = c & 1;

        if (c == 0) {
            const uint32_t qb = qbase + q_l;
            #pragma unroll
            for (int mt = 0; mt < 2; mt++) {
                LDM4(qa[mt][0][0], qa[mt][0][1], qa[mt][0][2], qa[mt][0][3],
                     qb + mt * 1280);
                LDM4(qa[mt][1][0], qa[mt][1][1], qa[mt][1][2], qa[mt][1][3],
                     qb + mt * 1280 + 32);
            }
        }

        // ---- K frags for this warp's 16 keys (2 ldmatrix) ----
        uint32_t kf[2][4];
        {
            const uint32_t kb = kbase + s * KBUF + w * 1280 + k_l;
            LDM4(kf[0][0], kf[0][1], kf[0][2], kf[0][3], kb);
            LDM4(kf[1][0], kf[1][1], kf[1][2], kf[1][3], kb + 32);
        }

        // ---- Scores: 32 queries x 16 keys ----
        float sf[2][2][4];
        #pragma unroll
        for (int mt = 0; mt < 2; mt++) {
            #pragma unroll
            for (int nt = 0; nt < 2; nt++) {
                sf[mt][nt][0] = 0.0f; sf[mt][nt][1] = 0.0f;
                sf[mt][nt][2] = 0.0f; sf[mt][nt][3] = 0.0f;
            }
            #pragma unroll
            for (int kk = 0; kk < 2; kk++) {
                mma_f16(sf[mt][0], qa[mt][kk][0], qa[mt][kk][1],
                        qa[mt][kk][2], qa[mt][kk][3], kf[kk][0], kf[kk][1]);
                mma_f16(sf[mt][1], qa[mt][kk][0], qa[mt][kk][1],
                        qa[mt][kk][2], qa[mt][kk][3], kf[kk][2], kf[kk][3]);
            }
        }

        // ---- mask + exp2 -> P A-frags ----
        int mb0 = 0, mb1 = 0, mb2 = 0, mb3 = 0;
        if (mask) {
            const int cb = s * 64 + 16 * w + 2 * t;
            mb0 = Msk[cb]; mb1 = Msk[cb + 1]; mb2 = Msk[cb + 8]; mb3 = Msk[cb + 9];
        }
        uint32_t pa[2][4];
        #pragma unroll
        for (int mt = 0; mt < 2; mt++) {
            if (mask) {
                if (mb0) { sf[mt][0][0] = -3.0e38f; sf[mt][0][2] = -3.0e38f; }
                if (mb1) { sf[mt][0][1] = -3.0e38f; sf[mt][0][3] = -3.0e38f; }
                if (mb2) { sf[mt][1][0] = -3.0e38f; sf[mt][1][2] = -3.0e38f; }
                if (mb3) { sf[mt][1][1] = -3.0e38f; sf[mt][1][3] = -3.0e38f; }
            }
            pa[mt][0] = ex2_h2(pack_h2(sf[mt][0][0] * C2EXP, sf[mt][0][1] * C2EXP));
            pa[mt][1] = ex2_h2(pack_h2(sf[mt][0][2] * C2EXP, sf[mt][0][3] * C2EXP));
            pa[mt][2] = ex2_h2(pack_h2(sf[mt][1][0] * C2EXP, sf[mt][1][1] * C2EXP));
            pa[mt][3] = ex2_h2(pack_h2(sf[mt][1][2] * C2EXP, sf[mt][1][3] * C2EXP));
        }

        // ---- V frags (2 ldmatrix.trans) + PV + ones-l ----
        uint32_t vb0[4], vb1[4];
        {
            const uint32_t vb = vbase + s * KBUF + w * 1280 + v_l;
            LDM4T(vb0[0], vb0[1], vb0[2], vb0[3], vb);
            LDM4T(vb1[0], vb1[1], vb1[2], vb1[3], vb + 640);
        }
        #pragma unroll
        for (int mt = 0; mt < 2; mt++) {
            #pragma unroll
            for (int nt = 0; nt < 4; nt++)
                mma_f16(of[mt][nt], pa[mt][0], pa[mt][1], pa[mt][2], pa[mt][3],
                        vb0[nt], vb1[nt]);
            mma_f16(lf[mt], pa[mt][0], pa[mt][1], pa[mt][2], pa[mt][3],
                    onesb, onesb);
        }
        __syncthreads();
    }

    // ---- cross-warp reduction (smem overlaid on dead Q/K/V buffers) ----
    #pragma unroll
    for (int mt = 0; mt < 2; mt++) {
        const int rlo = 16 * mt + g;
        #pragma unroll
        for (int nt = 0; nt < 4; nt++) {
            const int col = 8 * nt + 2 * t;
            *(float2*)&red[w][rlo][col]     = make_float2(of[mt][nt][0], of[mt][nt][1]);
            *(float2*)&red[w][rlo + 8][col] = make_float2(of[mt][nt][2], of[mt][nt][3]);
        }
        if (t == 0) {
            lred[w][rlo]     = lf[mt][0];
            lred[w][rlo + 8] = lf[mt][2];
        }
    }
    __syncthreads();

    // Finalize: thread -> (row rr = tid>>2, col segment cc = (tid&3)*8)
    const int rr = tid >> 2;
    const int cc = (tid & 3) * 8;
    const float l_tot = lred[0][rr] + lred[1][rr] + lred[2][rr] + lred[3][rr];
    float oacc[8];
    #pragma unroll
    for (int c4 = 0; c4 < 2; c4++) {
        const float4 v = *(const float4*)&red[0][rr][cc + c4 * 4];
        oacc[c4 * 4 + 0] = v.x; oacc[c4 * 4 + 1] = v.y;
        oacc[c4 * 4 + 2] = v.z; oacc[c4 * 4 + 3] = v.w;
    }
    #pragma unroll
    for (int ww = 1; ww < 4; ww++)
        #pragma unroll
        for (int c4 = 0; c4 < 2; c4++) {
            const float4 v = *(const float4*)&red[ww][rr][cc + c4 * 4];
            oacc[c4 * 4 + 0] += v.x; oacc[c4 * 4 + 1] += v.y;
            oacc[c4 * 4 + 2] += v.z; oacc[c4 * 4 + 3] += v.w;
        }

    if (norm) {
        const float inv = 1.0f / l_tot;
        __half* dst = &Oph[((size_t)b * Lq + q0 + rr) * 256 + h * 32 + cc];
        #pragma unroll
        for (int c2 = 0; c2 < 4; c2++)
            *(half2*)&dst[c2 * 2] =
                __floats2half2_rn(oacc[c2 * 2] * inv, oacc[c2 * 2 + 1] * inv);
    } else {
        float* dst = &Opf[((size_t)b * Lq + q0 + rr) * 256 + h * 32 + cc];
        #pragma unroll
        for (int c4 = 0; c4 < 2; c4++) {
            float4 v;
            v.x = oacc[c4 * 4 + 0]; v.y = oacc[c4 * 4 + 1];
            v.z = oacc[c4 * 4 + 2]; v.w = oacc[c4 * 4 + 3];
            *(float4*)&dst[c4 * 4] = v;
        }
        if (cc == 0)
            Lp[((size_t)b * HH + h) * NN + q0 + rr] = l_tot;
    }
}

// ---------------------------------------------------------------------------
// Combine dir1 split partials: att = f16((O0+O1)/(l0+l1))
// ---------------------------------------------------------------------------
__global__ void combine2(const float* __restrict__ po,
                         const float* __restrict__ pl,
                         __half* __restrict__ out)
{
    const int i4 = (blockIdx.x * 256 + threadIdx.x) * 4;
    if (i4 >= BB * NN * DD) return;
    const int b = i4 / (NN * DD);
    const int rem = i4 - b * NN * DD;
    const int q = rem / DD;
    const float l = pl[((size_t)b * HH + ((rem - q * DD) >> 5)) * NN + q] +
                    pl[(size_t)BB * HH * NN +
                       ((size_t)b * HH + ((rem - q * DD) >> 5)) * NN + q];
    const float inv = 1.0f / l;
    const float4 o0 = *(const float4*)&po[i4];
    const float4 o1 = *(const float4*)&po[BB * NN * DD + i4];
    *(half2*)&out[i4]     = __floats2half2_rn((o0.x + o1.x) * inv, (o0.y + o1.y) * inv);
    *(half2*)&out[i4 + 2] = __floats2half2_rn((o0.z + o1.z) * inv, (o0.w + o1.w) * inv);
}

// ---------------------------------------------------------------------------
extern "C" void kernel_launch(void* const* d_in, const int* in_sizes, int n_in,
                              void* d_out, int out_size)
{
    const float* amr      = (const float*)d_in[0];
    const int*   pad_mask = (const int*)  d_in[1];
    const float* vis      = (const float*)d_in[2];
    const float* W_amr_qk = (const float*)d_in[3];
    const float* W_amr_v  = (const float*)d_in[4];
    const float* W_vis_qk = (const float*)d_in[5];
    const float* W_vis_v  = (const float*)d_in[6];
    const float* W_amr_out= (const float*)d_in[7];
    const float* b_amr_out= (const float*)d_in[8];
    const float* W_vis_out= (const float*)d_in[9];
    const float* b_vis_out= (const float*)d_in[10];

    float* out_amr = (float*)d_out;
    float* out_vis = out_amr + (size_t)BB * NN * DD;

    __half *amr_h, *vis_h, *Wt, *amr_qk, *amr_v, *vis_qk, *vis_v, *amr_att, *vis_att;
    float *po, *pl;
    cudaGetSymbolAddress((void**)&amr_h,   g_amr_h);
    cudaGetSymbolAddress((void**)&vis_h,   g_vis_h);
    cudaGetSymbolAddress((void**)&Wt,      g_Wt);
    cudaGetSymbolAddress((void**)&amr_qk,  g_amr_qk);
    cudaGetSymbolAddress((void**)&amr_v,   g_amr_v);
    cudaGetSymbolAddress((void**)&vis_qk,  g_vis_qk);
    cudaGetSymbolAddress((void**)&vis_v,   g_vis_v);
    cudaGetSymbolAddress((void**)&amr_att, g_amr_att);
    cudaGetSymbolAddress((void**)&vis_att, g_vis_att);
    cudaGetSymbolAddress((void**)&po,      g_po);
    cudaGetSymbolAddress((void**)&pl,      g_pl);

    // Merged prep (features -> f16, weights transpose -> f16)
    prep_all<<<4992, 256>>>(amr, vis, W_amr_qk, W_amr_v, W_vis_qk, W_vis_v,
                            W_amr_out, W_vis_out, amr_h, vis_h, Wt);

    proj_all<<<dim3(4, 576), 128>>>(amr_h, vis_h, Wt, amr_qk, amr_v, vis_qk, vis_v);

    attn_all<<<5120, 128>>>(amr_qk, amr_v, vis_qk, vis_v, vis_att, po, pl, pad_mask);

    combine2<<<(BB*NN*DD) / 1024, 256>>>(po, pl, amr_att);

    epi_all<<<dim3(4, 288), 128>>>(amr_att, vis_att, Wt, b_amr_out, b_vis_out,
                                   amr, vis, out_amr, out_vis);
}

// round 14
// speedup vs baseline: 1.1543x; 1.1543x over previous
#include <cuda_runtime.h>
#include <cuda_fp16.h>
#include <stdint.h>

// Problem constants
#define BB 4
#define NN 512
#define MM 4096
#define DD 256
#define HH 8
#define C2EXP 0.25505551190558915f   // (1/sqrt(32)) * log2(e)

// ---------------------------------------------------------------------------
// Scratch (static device globals)
// ---------------------------------------------------------------------------
__device__ __half g_amr_h [BB*NN*DD];
__device__ __half g_vis_h [BB*MM*DD];
__device__ __half g_Wt    [6*DD*DD];          // transposed weights [n][k] f16
__device__ __half g_amr_qk[BB*NN*DD];         // pre-scaled by C2EXP
__device__ __half g_amr_v [BB*NN*DD];
__device__ __half g_vis_qk[BB*MM*DD];
__device__ __half g_vis_v [BB*MM*DD];
__device__ __half g_amr_att[BB*NN*DD];
__device__ __half g_vis_att[BB*MM*DD];
__device__ float  g_po[2*BB*NN*DD];           // dir1 split partial O
__device__ float  g_pl[2*BB*HH*NN];           // dir1 split partial l

// ---------------------------------------------------------------------------
// Helpers
// ---------------------------------------------------------------------------
__device__ __forceinline__ void mma_f16(float c[4],
                                        uint32_t a0, uint32_t a1,
                                        uint32_t a2, uint32_t a3,
                                        uint32_t b0, uint32_t b1) {
    asm volatile(
        "mma.sync.aligned.m16n8k16.row.col.f32.f16.f16.f32 "
        "{%0,%1,%2,%3}, {%4,%5,%6,%7}, {%8,%9}, {%0,%1,%2,%3};"
        : "+f"(c[0]), "+f"(c[1]), "+f"(c[2]), "+f"(c[3])
        : "r"(a0), "r"(a1), "r"(a2), "r"(a3), "r"(b0), "r"(b1));
}

__device__ __forceinline__ uint32_t smem_u32(const void* p) {
    return (uint32_t)__cvta_generic_to_shared(p);
}

#define CP16(dst_u32, src) \
    asm volatile("cp.async.ca.shared.global [%0], [%1], 16;" \
                 :: "r"(dst_u32), "l"(src))
#define CP_COMMIT() asm volatile("cp.async.commit_group;")
#define CP_WAIT(n)  asm volatile("cp.async.wait_group %0;" :: "n"(n))

#define LDM4(r0, r1, r2, r3, addr) \
    asm volatile("ldmatrix.sync.aligned.m8n8.x4.shared.b16 {%0,%1,%2,%3}, [%4];" \
                 : "=r"(r0), "=r"(r1), "=r"(r2), "=r"(r3) : "r"(addr))
#define LDM4T(r0, r1, r2, r3, addr) \
    asm volatile("ldmatrix.sync.aligned.m8n8.x4.trans.shared.b16 {%0,%1,%2,%3}, [%4];" \
                 : "=r"(r0), "=r"(r1), "=r"(r2), "=r"(r3) : "r"(addr))

__device__ __forceinline__ uint32_t pack_h2(float a, float b) {
    uint32_t r;
    asm("cvt.rn.f16x2.f32 %0, %1, %2;" : "=r"(r) : "f"(b), "f"(a));
    return r;
}
__device__ __forceinline__ uint32_t ex2_h2(uint32_t x) {
    uint32_t r;
    asm("ex2.approx.f16x2 %0, %1;" : "=r"(r) : "r"(x));
    return r;
}

// ---------------------------------------------------------------------------
// Merged prep: [0,4608) fp32->fp16 features; [4608,4992) weight transpose.
// ---------------------------------------------------------------------------
__global__ void prep_all(const float* __restrict__ amr, const float* __restrict__ vis,
                         const float* W0, const float* W1, const float* W2,
                         const float* W3, const float* W4, const float* W5,
                         __half* __restrict__ amr_h, __half* __restrict__ vis_h,
                         __half* __restrict__ Wt)
{
    __shared__ float tile[32][33];
    const int idb = blockIdx.x;
    const int tid = threadIdx.x;

    if (idb < 4608) {
        int i4 = (idb * 256 + tid) * 4;
        const int na = BB * NN * DD;
        const float* src; __half* dst;
        if (i4 < na) { src = amr; dst = amr_h; }
        else {
            i4 -= na;
            if (i4 >= BB * MM * DD) return;
            src = vis; dst = vis_h;
        }
        const float4 v = *(const float4*)&src[i4];
        *(half2*)&dst[i4]     = __floats2half2_rn(v.x, v.y);
        *(half2*)&dst[i4 + 2] = __floats2half2_rn(v.z, v.w);
    } else {
        const int z  = idb - 4608;           // 0..383
        const int mi = z >> 6;               // matrix 0..5
        const int bx = z & 7;                // n tile
        const int by = (z >> 3) & 7;         // k tile
        const float* Ws[6] = {W0, W1, W2, W3, W4, W5};
        const float* in = Ws[mi];
        __half* out = Wt + (size_t)mi * DD * DD;
        const int x0 = bx * 32, y0 = by * 32;
        const int tx = tid & 31, ty = tid >> 5;   // 32 x 8
        #pragma unroll
        for (int j = 0; j < 32; j += 8)
            tile[ty + j][tx] = in[(size_t)(y0 + ty + j) * DD + x0 + tx];
        __syncthreads();
        #pragma unroll
        for (int j = 0; j < 32; j += 8)
            out[(size_t)(x0 + ty + j) * DD + y0 + tx] = __float2half(tile[tx][ty + j]);
    }
}

// ---------------------------------------------------------------------------
// fp16 GEMM body: C[64x64] = alpha * (A[S,256] @ Wt[n][k]^T)
// 2-stage cp.async, ONE __syncthreads per k-chunk.
// ---------------------------------------------------------------------------
template <bool EPI>
__device__ __forceinline__ void gemm_body(const __half* __restrict__ A,
                                          const __half* __restrict__ W,
                                          const float* __restrict__ bias,
                                          const float* __restrict__ Xm,
                                          __half* __restrict__ Ch,
                                          float* __restrict__ Cf,
                                          int row0, int col0, float alpha)
{
    __shared__ __half Ab[2][64][72];
    __shared__ __half Wb[2][64][72];

    const int tid  = threadIdx.x;
    const int w    = tid >> 5;
    const int lane = tid & 31;
    const int g    = lane >> 2;
    const int t    = lane & 3;
    const int m    = lane >> 3;
    const int r    = lane & 7;
    const int sr   = tid >> 1;
    const int scb  = (tid & 1) * 32;

    const uint32_t abase = smem_u32(&Ab[0][0][0]);
    const uint32_t wbase = smem_u32(&Wb[0][0][0]);
    const uint32_t BUF = 64 * 72 * 2;
    const uint32_t a_l = (uint32_t)(((m & 1) * 8 + r) * 144 + (m >> 1) * 16);
    const uint32_t w_l = (uint32_t)(((m >> 1) * 8 + r) * 144 + (m & 1) * 16);

    float acc[8][4];
    #pragma unroll
    for (int nt = 0; nt < 8; nt++)
        #pragma unroll
        for (int i = 0; i < 4; i++) acc[nt][i] = 0.0f;

    auto stage = [&](int s, int kc) {
        const __half* ap = &A[(size_t)(row0 + sr) * 256 + kc + scb];
        const __half* wp = &W[(size_t)(col0 + sr) * 256 + kc + scb];
        #pragma unroll
        for (int o = 0; o < 32; o += 8) {
            CP16(smem_u32(&Ab[s][sr][scb + o]), ap + o);
            CP16(smem_u32(&Wb[s][sr][scb + o]), wp + o);
        }
    };

    stage(0, 0); CP_COMMIT();

    for (int c = 0; c < 4; c++) {
        CP_WAIT(0);
        __syncthreads();
        if (c < 3) { stage((c + 1) & 1, (c + 1) * 64); CP_COMMIT(); }
        const int s = c & 1;
        const uint32_t ab = abase + s * BUF + w * 2304 + a_l;
        const uint32_t wb = wbase + s * BUF + w_l;
        #pragma unroll
        for (int kk = 0; kk < 4; kk++) {
            uint32_t a0, a1, a2, a3;
            LDM4(a0, a1, a2, a3, ab + kk * 32);
            #pragma unroll
            for (int j = 0; j < 4; j++) {
                uint32_t b00, b01, b10, b11;
                LDM4(b00, b01, b10, b11, wb + j * 2304 + kk * 32);
                mma_f16(acc[2 * j],     a0, a1, a2, a3, b00, b01);
                mma_f16(acc[2 * j + 1], a0, a1, a2, a3, b10, b11);
            }
        }
    }

    const size_t r_lo = (size_t)(row0 + 16 * w + g);
    const size_t r_hi = r_lo + 8;
    #pragma unroll
    for (int nt = 0; nt < 8; nt++) {
        const int col = col0 + nt * 8 + 2 * t;
        if (EPI) {
            const float2 bv  = *(const float2*)&bias[col];
            const float2 xlo = *(const float2*)&Xm[r_lo * 256 + col];
            const float2 xhi = *(const float2*)&Xm[r_hi * 256 + col];
            float2 lo, hi;
            lo.x = (acc[nt][0] + bv.x) * xlo.x; lo.y = (acc[nt][1] + bv.y) * xlo.y;
            hi.x = (acc[nt][2] + bv.x) * xhi.x; hi.y = (acc[nt][3] + bv.y) * xhi.y;
            *(float2*)&Cf[r_lo * 256 + col] = lo;
            *(float2*)&Cf[r_hi * 256 + col] = hi;
        } else {
            *(half2*)&Ch[r_lo * 256 + col] =
                __floats2half2_rn(acc[nt][0] * alpha, acc[nt][1] * alpha);
            *(half2*)&Ch[r_hi * 256 + col] =
                __floats2half2_rn(acc[nt][2] * alpha, acc[nt][3] * alpha);
        }
    }
}

__global__ void __launch_bounds__(128) proj_all(const __half* amr_h, const __half* vis_h,
                                                const __half* Wt,
                                                __half* amr_qk, __half* amr_v,
                                                __half* vis_qk, __half* vis_v)
{
    const int y = blockIdx.y;
    const int col0 = blockIdx.x * 64;
    const __half *A, *W; __half* C; int row0; float alpha = 1.0f;
    if      (y < 32)  { A = amr_h; W = Wt + 0 * DD * DD; C = amr_qk; row0 = y * 64;
                        alpha = C2EXP; }                     // fold softmax scale
    else if (y < 64)  { A = amr_h; W = Wt + 1 * DD * DD; C = amr_v;  row0 = (y - 32) * 64; }
    else if (y < 320) { A = vis_h; W = Wt + 2 * DD * DD; C = vis_qk; row0 = (y - 64) * 64; }
    else              { A = vis_h; W = Wt + 3 * DD * DD; C = vis_v;  row0 = (y - 320) * 64; }
    gemm_body<false>(A, W, nullptr, nullptr, C, nullptr, row0, col0, alpha);
}

__global__ void __launch_bounds__(128) epi_all(const __half* amr_att, const __half* vis_att,
                                               const __half* Wt,
                                               const float* b_amr, const float* b_vis,
                                               const float* amr_f, const float* vis_f,
                                               float* out_amr, float* out_vis)
{
    const int y = blockIdx.y;
    const int col0 = blockIdx.x * 64;
    const __half *A, *W; const float *bias, *Xm; float* C; int row0;
    if (y < 32) { A = amr_att; W = Wt + 4 * DD * DD; bias = b_amr; Xm = amr_f;
                  C = out_amr; row0 = y * 64; }
    else        { A = vis_att; W = Wt + 5 * DD * DD; bias = b_vis; Xm = vis_f;
                  C = out_vis; row0 = (y - 32) * 64; }
    gemm_body<true>(A, W, bias, Xm, nullptr, C, row0, col0, 1.0f);
}

// ---------------------------------------------------------------------------
// Fused attention — key-split warps, 64-query tiles, with:
//   * scores pre-scaled via amr_qk (no per-element FMUL before exp2)
//   * ONE __syncthreads per chunk (stage(c+1) issued after top sync)
// Warp w owns keys [16w,16w+16) of each 64-key chunk, ALL 64 queries.
// Grid 2560 1D: [0,512) dir1 (split-KV x2, unnorm partials), [512,2560) dir2.
// ---------------------------------------------------------------------------
__global__ void __launch_bounds__(128, 3) attn_all(
    const __half* __restrict__ amr_qk, const __half* __restrict__ amr_v,
    const __half* __restrict__ vis_qk, const __half* __restrict__ vis_v,
    __half* __restrict__ vis_att, float* __restrict__ po, float* __restrict__ pl,
    const int* __restrict__ pad_mask)
{
    // main phase [Qs|Kb|Vb|Msk] = 26112 B; reduce overlay = 37888 B
    __shared__ __align__(16) char SM[37888];
    int*   Msk  = reinterpret_cast<int*>(SM + 25600);          // [2][64]
    float (*red)[64][36] = reinterpret_cast<float(*)[64][36]>(SM);
    float (*lred)[64]    = reinterpret_cast<float(*)[64]>(SM + 36864);

    const uint32_t qbase = smem_u32(SM);            // Qs: half[64][40]
    const uint32_t kbase = smem_u32(SM + 5120);     // Kb: half[2][64][40]
    const uint32_t vbase = smem_u32(SM + 15360);    // Vb: half[2][64][40]
    const uint32_t KBUF = 64 * 40 * 2;              // 5120

    // --- decode block role ---
    const __half *Qp, *Kp, *Vp;
    int Lq, LkT, kv0, nch, b, h, q0, norm;
    const int* mask;
    float* Opf = nullptr; float* Lp = nullptr; __half* Oph = nullptr;
    {
        const int id = blockIdx.x;
        if (id < 512) {
            b = id & 3; h = (id >> 2) & 7; q0 = ((id >> 5) & 7) * 64;
            const int sp = id >> 8;
            Qp = amr_qk; Kp = vis_qk; Vp = vis_v;
            Lq = NN; LkT = MM; kv0 = sp * (MM / 2); nch = (MM / 2) / 64;
            mask = nullptr; norm = 0;
            Opf = po + (size_t)sp * BB * NN * DD;
            Lp  = pl + sp * BB * HH * NN;
        } else {
            const int j = id - 512;
            b = j & 3; h = (j >> 2) & 7; q0 = (j >> 5) * 64;
            Qp = vis_qk; Kp = amr_qk; Vp = amr_v;
            Lq = MM; LkT = NN; kv0 = 0; nch = NN / 64;
            mask = pad_mask; norm = 1;
            Oph = vis_att;
        }
    }

    const int tid  = threadIdx.x;
    const int w    = tid >> 5;
    const int lane = tid & 31;
    const int g    = lane >> 2;
    const int t    = lane & 3;
    const int m    = lane >> 3;
    const int r    = lane & 7;
    const int sr   = tid >> 1;
    const int scb  = (tid & 1) * 16;

    const uint32_t q_l = (uint32_t)(((m & 1) * 8 + r) * 80 + (m >> 1) * 16);
    const uint32_t k_l = (uint32_t)(((m >> 1) * 8 + r) * 80 + (m & 1) * 16);
    const uint32_t v_l = (uint32_t)(r * 80 + m * 16);
    const uint32_t onesb = (g == 0) ? 0x3C003C00u : 0u;   // B col 0 = ones

    __half (*QsW)[40]     = reinterpret_cast<__half(*)[40]>(SM);
    __half (*KbW)[64][40] = reinterpret_cast<__half(*)[64][40]>(SM + 5120);
    __half (*VbW)[64][40] = reinterpret_cast<__half(*)[64][40]>(SM + 15360);

    auto stageKV = [&](int s, int kc) {
        const size_t base = ((size_t)b * LkT + kv0 + kc + sr) * 256 + h * 32 + scb;
        CP16(smem_u32(&KbW[s][sr][scb]),     &Kp[base]);
        CP16(smem_u32(&KbW[s][sr][scb + 8]), &Kp[base + 8]);
        CP16(smem_u32(&VbW[s][sr][scb]),     &Vp[base]);
        CP16(smem_u32(&VbW[s][sr][scb + 8]), &Vp[base + 8]);
        if (mask && tid < 16)
            CP16(smem_u32(&Msk[s * 64 + tid * 4]), &mask[b * LkT + kv0 + kc + tid * 4]);
    };

    // Stage Q + first KV chunk (group 0)
    {
        const size_t qb = ((size_t)b * Lq + q0 + sr) * 256 + h * 32 + scb;
        CP16(smem_u32(&QsW[sr][scb]),     &Qp[qb]);
        CP16(smem_u32(&QsW[sr][scb + 8]), &Qp[qb + 8]);
    }
    stageKV(0, 0);
    CP_COMMIT();

    uint32_t qa[4][2][4];          // [m-tile][kk][frag]
    float of[4][4][4];             // [m-tile][n-tile][frag] partial O
    float lf[4][4];                // [m-tile][frag]        partial l
    #pragma unroll
    for (int mt = 0; mt < 4; mt++) {
        #pragma unroll
        for (int nt = 0; nt < 4; nt++)
            #pragma unroll
            for (int i = 0; i < 4; i++) of[mt][nt][i] = 0.0f;
        #pragma unroll
        for (int i = 0; i < 4; i++) lf[mt][i] = 0.0f;
    }

    for (int c = 0; c < nch; c++) {
        CP_WAIT(0);            // chunk c's group complete
        __syncthreads();       // all warps done reading the buffer we refill
        if (c + 1 < nch) { stageKV((c + 1) & 1, (c + 1) * 64); CP_COMMIT(); }
        const int s = c & 1;

        if (c == 0) {
            const uint32_t qb = qbase + q_l;
            #pragma unroll
            for (int mt = 0; mt < 4; mt++) {
                LDM4(qa[mt][0][0], qa[mt][0][1], qa[mt][0][2], qa[mt][0][3],
                     qb + mt * 1280);
                LDM4(qa[mt][1][0], qa[mt][1][1], qa[mt][1][2], qa[mt][1][3],
                     qb + mt * 1280 + 32);
            }
        }

        // ---- K frags for this warp's 16 keys (2 ldmatrix) ----
        uint32_t kf[2][4];
        {
            const uint32_t kb = kbase + s * KBUF + w * 1280 + k_l;
            LDM4(kf[0][0], kf[0][1], kf[0][2], kf[0][3], kb);
            LDM4(kf[1][0], kf[1][1], kf[1][2], kf[1][3], kb + 32);
        }

        // ---- Scores: 64 queries x 16 keys (already scaled by C2EXP) ----
        float sf[4][2][4];
        #pragma unroll
        for (int mt = 0; mt < 4; mt++) {
            #pragma unroll
            for (int nt = 0; nt < 2; nt++) {
                sf[mt][nt][0] = 0.0f; sf[mt][nt][1] = 0.0f;
                sf[mt][nt][2] = 0.0f; sf[mt][nt][3] = 0.0f;
            }
            #pragma unroll
            for (int kk = 0; kk < 2; kk++) {
                mma_f16(sf[mt][0], qa[mt][kk][0], qa[mt][kk][1],
                        qa[mt][kk][2], qa[mt][kk][3], kf[kk][0], kf[kk][1]);
                mma_f16(sf[mt][1], qa[mt][kk][0], qa[mt][kk][1],
                        qa[mt][kk][2], qa[mt][kk][3], kf[kk][2], kf[kk][3]);
            }
        }

        // ---- mask + exp2 -> P A-frags (no scale multiply needed) ----
        int mb0 = 0, mb1 = 0, mb2 = 0, mb3 = 0;
        if (mask) {
            const int cb = s * 64 + 16 * w + 2 * t;
            mb0 = Msk[cb]; mb1 = Msk[cb + 1]; mb2 = Msk[cb + 8]; mb3 = Msk[cb + 9];
        }
        uint32_t pa[4][4];
        #pragma unroll
        for (int mt = 0; mt < 4; mt++) {
            if (mask) {
                if (mb0) { sf[mt][0][0] = -3.0e38f; sf[mt][0][2] = -3.0e38f; }
                if (mb1) { sf[mt][0][1] = -3.0e38f; sf[mt][0][3] = -3.0e38f; }
                if (mb2) { sf[mt][1][0] = -3.0e38f; sf[mt][1][2] = -3.0e38f; }
                if (mb3) { sf[mt][1][1] = -3.0e38f; sf[mt][1][3] = -3.0e38f; }
            }
            pa[mt][0] = ex2_h2(pack_h2(sf[mt][0][0], sf[mt][0][1]));
            pa[mt][1] = ex2_h2(pack_h2(sf[mt][0][2], sf[mt][0][3]));
            pa[mt][2] = ex2_h2(pack_h2(sf[mt][1][0], sf[mt][1][1]));
            pa[mt][3] = ex2_h2(pack_h2(sf[mt][1][2], sf[mt][1][3]));
        }

        // ---- V frags (2 ldmatrix.trans) + PV + ones-l ----
        uint32_t vb0[4], vb1[4];
        {
            const uint32_t vb = vbase + s * KBUF + w * 1280 + v_l;
            LDM4T(vb0[0], vb0[1], vb0[2], vb0[3], vb);
            LDM4T(vb1[0], vb1[1], vb1[2], vb1[3], vb + 640);
        }
        #pragma unroll
        for (int mt = 0; mt < 4; mt++) {
            #pragma unroll
            for (int nt = 0; nt < 4; nt++)
                mma_f16(of[mt][nt], pa[mt][0], pa[mt][1], pa[mt][2], pa[mt][3],
                        vb0[nt], vb1[nt]);
            mma_f16(lf[mt], pa[mt][0], pa[mt][1], pa[mt][2], pa[mt][3],
                    onesb, onesb);
        }
    }
    __syncthreads();   // all compute done before overlaying reduce buffers

    // ---- cross-warp reduction (smem overlaid on dead Q/K/V buffers) ----
    #pragma unroll
    for (int mt = 0; mt < 4; mt++) {
        const int rlo = 16 * mt + g;
        #pragma unroll
        for (int nt = 0; nt < 4; nt++) {
            const int col = 8 * nt + 2 * t;
            *(float2*)&red[w][rlo][col]     = make_float2(of[mt][nt][0], of[mt][nt][1]);
            *(float2*)&red[w][rlo + 8][col] = make_float2(of[mt][nt][2], of[mt][nt][3]);
        }
        if (t == 0) {
            lred[w][rlo]     = lf[mt][0];
            lred[w][rlo + 8] = lf[mt][2];
        }
    }
    __syncthreads();

    // Each warp finalizes 16 rows; lane -> (row, col-half)
    const int rr = 16 * w + (lane >> 1);
    const int cc = (lane & 1) * 16;
    const float l_tot = lred[0][rr] + lred[1][rr] + lred[2][rr] + lred[3][rr];
    float oacc[16];
    #pragma unroll
    for (int c4 = 0; c4 < 4; c4++) {
        const float4 v = *(const float4*)&red[0][rr][cc + c4 * 4];
        oacc[c4 * 4 + 0] = v.x; oacc[c4 * 4 + 1] = v.y;
        oacc[c4 * 4 + 2] = v.z; oacc[c4 * 4 + 3] = v.w;
    }
    #pragma unroll
    for (int ww = 1; ww < 4; ww++)
        #pragma unroll
        for (int c4 = 0; c4 < 4; c4++) {
            const float4 v = *(const float4*)&red[ww][rr][cc + c4 * 4];
            oacc[c4 * 4 + 0] += v.x; oacc[c4 * 4 + 1] += v.y;
            oacc[c4 * 4 + 2] += v.z; oacc[c4 * 4 + 3] += v.w;
        }

    if (norm) {
        const float inv = 1.0f / l_tot;
        __half* dst = &Oph[((size_t)b * Lq + q0 + rr) * 256 + h * 32 + cc];
        #pragma unroll
        for (int c2 = 0; c2 < 8; c2++)
            *(half2*)&dst[c2 * 2] =
                __floats2half2_rn(oacc[c2 * 2] * inv, oacc[c2 * 2 + 1] * inv);
    } else {
        float* dst = &Opf[((size_t)b * Lq + q0 + rr) * 256 + h * 32 + cc];
        #pragma unroll
        for (int c4 = 0; c4 < 4; c4++) {
            float4 v;
            v.x = oacc[c4 * 4 + 0]; v.y = oacc[c4 * 4 + 1];
            v.z = oacc[c4 * 4 + 2]; v.w = oacc[c4 * 4 + 3];
            *(float4*)&dst[c4 * 4] = v;
        }
        if (cc == 0)
            Lp[((size_t)b * HH + h) * NN + q0 + rr] = l_tot;
    }
}

// ---------------------------------------------------------------------------
// Combine dir1 split partials: att = f16((O0+O1)/(l0+l1))
// ---------------------------------------------------------------------------
__global__ void combine2(const float* __restrict__ po,
                         const float* __restrict__ pl,
                         __half* __restrict__ out)
{
    const int i4 = (blockIdx.x * 256 + threadIdx.x) * 4;
    if (i4 >= BB * NN * DD) return;
    const int b = i4 / (NN * DD);
    const int rem = i4 - b * NN * DD;
    const int q = rem / DD;
    const float l = pl[((size_t)b * HH + ((rem - q * DD) >> 5)) * NN + q] +
                    pl[(size_t)BB * HH * NN +
                       ((size_t)b * HH + ((rem - q * DD) >> 5)) * NN + q];
    const float inv = 1.0f / l;
    const float4 o0 = *(const float4*)&po[i4];
    const float4 o1 = *(const float4*)&po[BB * NN * DD + i4];
    *(half2*)&out[i4]     = __floats2half2_rn((o0.x + o1.x) * inv, (o0.y + o1.y) * inv);
    *(half2*)&out[i4 + 2] = __floats2half2_rn((o0.z + o1.z) * inv, (o0.w + o1.w) * inv);
}

// ---------------------------------------------------------------------------
extern "C" void kernel_launch(void* const* d_in, const int* in_sizes, int n_in,
                              void* d_out, int out_size)
{
    const float* amr      = (const float*)d_in[0];
    const int*   pad_mask = (const int*)  d_in[1];
    const float* vis      = (const float*)d_in[2];
    const float* W_amr_qk = (const float*)d_in[3];
    const float* W_amr_v  = (const float*)d_in[4];
    const float* W_vis_qk = (const float*)d_in[5];
    const float* W_vis_v  = (const float*)d_in[6];
    const float* W_amr_out= (const float*)d_in[7];
    const float* b_amr_out= (const float*)d_in[8];
    const float* W_vis_out= (const float*)d_in[9];
    const float* b_vis_out= (const float*)d_in[10];

    float* out_amr = (float*)d_out;
    float* out_vis = out_amr + (size_t)BB * NN * DD;

    __half *amr_h, *vis_h, *Wt, *amr_qk, *amr_v, *vis_qk, *vis_v, *amr_att, *vis_att;
    float *po, *pl;
    cudaGetSymbolAddress((void**)&amr_h,   g_amr_h);
    cudaGetSymbolAddress((void**)&vis_h,   g_vis_h);
    cudaGetSymbolAddress((void**)&Wt,      g_Wt);
    cudaGetSymbolAddress((void**)&amr_qk,  g_amr_qk);
    cudaGetSymbolAddress((void**)&amr_v,   g_amr_v);
    cudaGetSymbolAddress((void**)&vis_qk,  g_vis_qk);
    cudaGetSymbolAddress((void**)&vis_v,   g_vis_v);
    cudaGetSymbolAddress((void**)&amr_att, g_amr_att);
    cudaGetSymbolAddress((void**)&vis_att, g_vis_att);
    cudaGetSymbolAddress((void**)&po,      g_po);
    cudaGetSymbolAddress((void**)&pl,      g_pl);

    prep_all<<<4992, 256>>>(amr, vis, W_amr_qk, W_amr_v, W_vis_qk, W_vis_v,
                            W_amr_out, W_vis_out, amr_h, vis_h, Wt);

    proj_all<<<dim3(4, 576), 128>>>(amr_h, vis_h, Wt, amr_qk, amr_v, vis_qk, vis_v);

    attn_all<<<2560, 128>>>(amr_qk, amr_v, vis_qk, vis_v, vis_att, po, pl, pad_mask);

    combine2<<<(BB*NN*DD) / 1024, 256>>>(po, pl, amr_att);

    epi_all<<<dim3(4, 288), 128>>>(amr_att, vis_att, Wt, b_amr_out, b_vis_out,
                                   amr, vis, out_amr, out_vis);
}

// round 15
// speedup vs baseline: 1.1689x; 1.0126x over previous
#include <cuda_runtime.h>
#include <cuda_fp16.h>
#include <stdint.h>

// Problem constants
#define BB 4
#define NN 512
#define MM 4096
#define DD 256
#define HH 8
#define C2EXP 0.25505551190558915f   // (1/sqrt(32)) * log2(e)

// ---------------------------------------------------------------------------
// Scratch (static device globals)
// ---------------------------------------------------------------------------
__device__ __half g_amr_h [BB*NN*DD];
__device__ __half g_vis_h [BB*MM*DD];
__device__ __half g_Wt    [6*DD*DD];          // transposed weights [n][k] f16
__device__ __half g_amr_qk[BB*NN*DD];         // pre-scaled by C2EXP
__device__ __half g_amr_v [BB*NN*DD];
__device__ __half g_vis_qk[BB*MM*DD];
__device__ __half g_vis_v [BB*MM*DD];
__device__ __half g_amr_att[BB*NN*DD];
__device__ __half g_vis_att[BB*MM*DD];
__device__ float  g_po[2*BB*NN*DD];           // dir1 split partial O
__device__ float  g_pl[2*BB*HH*NN];           // dir1 split partial l

// ---------------------------------------------------------------------------
// Helpers
// ---------------------------------------------------------------------------
__device__ __forceinline__ void mma_f16(float c[4],
                                        uint32_t a0, uint32_t a1,
                                        uint32_t a2, uint32_t a3,
                                        uint32_t b0, uint32_t b1) {
    asm volatile(
        "mma.sync.aligned.m16n8k16.row.col.f32.f16.f16.f32 "
        "{%0,%1,%2,%3}, {%4,%5,%6,%7}, {%8,%9}, {%0,%1,%2,%3};"
        : "+f"(c[0]), "+f"(c[1]), "+f"(c[2]), "+f"(c[3])
        : "r"(a0), "r"(a1), "r"(a2), "r"(a3), "r"(b0), "r"(b1));
}

__device__ __forceinline__ uint32_t smem_u32(const void* p) {
    return (uint32_t)__cvta_generic_to_shared(p);
}

#define CP16(dst_u32, src) \
    asm volatile("cp.async.ca.shared.global [%0], [%1], 16;" \
                 :: "r"(dst_u32), "l"(src))
#define CP_COMMIT() asm volatile("cp.async.commit_group;")
#define CP_WAIT(n)  asm volatile("cp.async.wait_group %0;" :: "n"(n))

#define LDM4(r0, r1, r2, r3, addr) \
    asm volatile("ldmatrix.sync.aligned.m8n8.x4.shared.b16 {%0,%1,%2,%3}, [%4];" \
                 : "=r"(r0), "=r"(r1), "=r"(r2), "=r"(r3) : "r"(addr))
#define LDM4T(r0, r1, r2, r3, addr) \
    asm volatile("ldmatrix.sync.aligned.m8n8.x4.trans.shared.b16 {%0,%1,%2,%3}, [%4];" \
                 : "=r"(r0), "=r"(r1), "=r"(r2), "=r"(r3) : "r"(addr))

__device__ __forceinline__ uint32_t pack_h2(float a, float b) {
    uint32_t r;
    asm("cvt.rn.f16x2.f32 %0, %1, %2;" : "=r"(r) : "f"(b), "f"(a));
    return r;
}
__device__ __forceinline__ uint32_t ex2_h2(uint32_t x) {
    uint32_t r;
    asm("ex2.approx.f16x2 %0, %1;" : "=r"(r) : "r"(x));
    return r;
}

// ---------------------------------------------------------------------------
// Merged prep: [0,4608) fp32->fp16 features; [4608,4992) weight transpose.
// ---------------------------------------------------------------------------
__global__ void prep_all(const float* __restrict__ amr, const float* __restrict__ vis,
                         const float* W0, const float* W1, const float* W2,
                         const float* W3, const float* W4, const float* W5,
                         __half* __restrict__ amr_h, __half* __restrict__ vis_h,
                         __half* __restrict__ Wt)
{
    __shared__ float tile[32][33];
    const int idb = blockIdx.x;
    const int tid = threadIdx.x;

    if (idb < 4608) {
        int i4 = (idb * 256 + tid) * 4;
        const int na = BB * NN * DD;
        const float* src; __half* dst;
        if (i4 < na) { src = amr; dst = amr_h; }
        else {
            i4 -= na;
            if (i4 >= BB * MM * DD) return;
            src = vis; dst = vis_h;
        }
        const float4 v = *(const float4*)&src[i4];
        *(half2*)&dst[i4]     = __floats2half2_rn(v.x, v.y);
        *(half2*)&dst[i4 + 2] = __floats2half2_rn(v.z, v.w);
    } else {
        const int z  = idb - 4608;           // 0..383
        const int mi = z >> 6;               // matrix 0..5
        const int bx = z & 7;                // n tile
        const int by = (z >> 3) & 7;         // k tile
        const float* Ws[6] = {W0, W1, W2, W3, W4, W5};
        const float* in = Ws[mi];
        __half* out = Wt + (size_t)mi * DD * DD;
        const int x0 = bx * 32, y0 = by * 32;
        const int tx = tid & 31, ty = tid >> 5;   // 32 x 8
        #pragma unroll
        for (int j = 0; j < 32; j += 8)
            tile[ty + j][tx] = in[(size_t)(y0 + ty + j) * DD + x0 + tx];
        __syncthreads();
        #pragma unroll
        for (int j = 0; j < 32; j += 8)
            out[(size_t)(x0 + ty + j) * DD + y0 + tx] = __float2half(tile[tx][ty + j]);
    }
}

// ---------------------------------------------------------------------------
// fp16 GEMM body: C[64x64] = alpha * (A[S,256] @ Wt[n][k]^T)
// 2-stage cp.async, ONE __syncthreads per k-chunk. (unchanged from R14)
// ---------------------------------------------------------------------------
template <bool EPI>
__device__ __forceinline__ void gemm_body(const __half* __restrict__ A,
                                          const __half* __restrict__ W,
                                          const float* __restrict__ bias,
                                          const float* __restrict__ Xm,
                                          __half* __restrict__ Ch,
                                          float* __restrict__ Cf,
                                          int row0, int col0, float alpha)
{
    __shared__ __half Ab[2][64][72];
    __shared__ __half Wb[2][64][72];

    const int tid  = threadIdx.x;
    const int w    = tid >> 5;
    const int lane = tid & 31;
    const int g    = lane >> 2;
    const int t    = lane & 3;
    const int m    = lane >> 3;
    const int r    = lane & 7;
    const int sr   = tid >> 1;
    const int scb  = (tid & 1) * 32;

    const uint32_t abase = smem_u32(&Ab[0][0][0]);
    const uint32_t wbase = smem_u32(&Wb[0][0][0]);
    const uint32_t BUF = 64 * 72 * 2;
    const uint32_t a_l = (uint32_t)(((m & 1) * 8 + r) * 144 + (m >> 1) * 16);
    const uint32_t w_l = (uint32_t)(((m >> 1) * 8 + r) * 144 + (m & 1) * 16);

    float acc[8][4];
    #pragma unroll
    for (int nt = 0; nt < 8; nt++)
        #pragma unroll
        for (int i = 0; i < 4; i++) acc[nt][i] = 0.0f;

    auto stage = [&](int s, int kc) {
        const __half* ap = &A[(size_t)(row0 + sr) * 256 + kc + scb];
        const __half* wp = &W[(size_t)(col0 + sr) * 256 + kc + scb];
        #pragma unroll
        for (int o = 0; o < 32; o += 8) {
            CP16(smem_u32(&Ab[s][sr][scb + o]), ap + o);
            CP16(smem_u32(&Wb[s][sr][scb + o]), wp + o);
        }
    };

    stage(0, 0); CP_COMMIT();

    for (int c = 0; c < 4; c++) {
        CP_WAIT(0);
        __syncthreads();
        if (c < 3) { stage((c + 1) & 1, (c + 1) * 64); CP_COMMIT(); }
        const int s = c & 1;
        const uint32_t ab = abase + s * BUF + w * 2304 + a_l;
        const uint32_t wb = wbase + s * BUF + w_l;
        #pragma unroll
        for (int kk = 0; kk < 4; kk++) {
            uint32_t a0, a1, a2, a3;
            LDM4(a0, a1, a2, a3, ab + kk * 32);
            #pragma unroll
            for (int j = 0; j < 4; j++) {
                uint32_t b00, b01, b10, b11;
                LDM4(b00, b01, b10, b11, wb + j * 2304 + kk * 32);
                mma_f16(acc[2 * j],     a0, a1, a2, a3, b00, b01);
                mma_f16(acc[2 * j + 1], a0, a1, a2, a3, b10, b11);
            }
        }
    }

    const size_t r_lo = (size_t)(row0 + 16 * w + g);
    const size_t r_hi = r_lo + 8;
    #pragma unroll
    for (int nt = 0; nt < 8; nt++) {
        const int col = col0 + nt * 8 + 2 * t;
        if (EPI) {
            const float2 bv  = *(const float2*)&bias[col];
            const float2 xlo = *(const float2*)&Xm[r_lo * 256 + col];
            const float2 xhi = *(const float2*)&Xm[r_hi * 256 + col];
            float2 lo, hi;
            lo.x = (acc[nt][0] + bv.x) * xlo.x; lo.y = (acc[nt][1] + bv.y) * xlo.y;
            hi.x = (acc[nt][2] + bv.x) * xhi.x; hi.y = (acc[nt][3] + bv.y) * xhi.y;
            *(float2*)&Cf[r_lo * 256 + col] = lo;
            *(float2*)&Cf[r_hi * 256 + col] = hi;
        } else {
            *(half2*)&Ch[r_lo * 256 + col] =
                __floats2half2_rn(acc[nt][0] * alpha, acc[nt][1] * alpha);
            *(half2*)&Ch[r_hi * 256 + col] =
                __floats2half2_rn(acc[nt][2] * alpha, acc[nt][3] * alpha);
        }
    }
}

__global__ void __launch_bounds__(128) proj_all(const __half* amr_h, const __half* vis_h,
                                                const __half* Wt,
                                                __half* amr_qk, __half* amr_v,
                                                __half* vis_qk, __half* vis_v)
{
    const int y = blockIdx.y;
    const int col0 = blockIdx.x * 64;
    const __half *A, *W; __half* C; int row0; float alpha = 1.0f;
    if      (y < 32)  { A = amr_h; W = Wt + 0 * DD * DD; C = amr_qk; row0 = y * 64;
                        alpha = C2EXP; }                     // fold softmax scale
    else if (y < 64)  { A = amr_h; W = Wt + 1 * DD * DD; C = amr_v;  row0 = (y - 32) * 64; }
    else if (y < 320) { A = vis_h; W = Wt + 2 * DD * DD; C = vis_qk; row0 = (y - 64) * 64; }
    else              { A = vis_h; W = Wt + 3 * DD * DD; C = vis_v;  row0 = (y - 320) * 64; }
    gemm_body<false>(A, W, nullptr, nullptr, C, nullptr, row0, col0, alpha);
}

__global__ void __launch_bounds__(128) epi_all(const __half* amr_att, const __half* vis_att,
                                               const __half* Wt,
                                               const float* b_amr, const float* b_vis,
                                               const float* amr_f, const float* vis_f,
                                               float* out_amr, float* out_vis)
{
    const int y = blockIdx.y;
    const int col0 = blockIdx.x * 64;
    const __half *A, *W; const float *bias, *Xm; float* C; int row0;
    if (y < 32) { A = amr_att; W = Wt + 4 * DD * DD; bias = b_amr; Xm = amr_f;
                  C = out_amr; row0 = y * 64; }
    else        { A = vis_att; W = Wt + 5 * DD * DD; bias = b_vis; Xm = vis_f;
                  C = out_vis; row0 = (y - 32) * 64; }
    gemm_body<true>(A, W, bias, Xm, nullptr, C, row0, col0, 1.0f);
}

// ---------------------------------------------------------------------------
// Fused attention — key-split warps + PER-WARP STAGING (no barrier in loop).
// Warp w owns keys [16w,16w+16): it stages ONLY those K/V rows with its own
// cp.async groups and waits only on itself. Block barriers: one at c==0 (for
// the shared Q tile), two at the final cross-warp reduction. Mask via LDG.
// Grid 2560 1D: [0,512) dir1 (split-KV x2, unnorm partials), [512,2560) dir2.
// ---------------------------------------------------------------------------
__global__ void __launch_bounds__(128, 3) attn_all(
    const __half* __restrict__ amr_qk, const __half* __restrict__ amr_v,
    const __half* __restrict__ vis_qk, const __half* __restrict__ vis_v,
    __half* __restrict__ vis_att, float* __restrict__ po, float* __restrict__ pl,
    const int* __restrict__ pad_mask)
{
    // main phase [Qs|Kb|Vb] = 25600 B; reduce overlay = 37888 B
    __shared__ __align__(16) char SM[37888];
    float (*red)[64][36] = reinterpret_cast<float(*)[64][36]>(SM);
    float (*lred)[64]    = reinterpret_cast<float(*)[64]>(SM + 36864);

    const uint32_t qbase = smem_u32(SM);            // Qs: half[64][40]
    const uint32_t kbase = smem_u32(SM + 5120);     // Kb: half[2][64][40]
    const uint32_t vbase = smem_u32(SM + 15360);    // Vb: half[2][64][40]
    const uint32_t KBUF = 64 * 40 * 2;              // 5120

    // --- decode block role ---
    const __half *Qp, *Kp, *Vp;
    int Lq, LkT, kv0, nch, b, h, q0, norm;
    const int* mask;
    float* Opf = nullptr; float* Lp = nullptr; __half* Oph = nullptr;
    {
        const int id = blockIdx.x;
        if (id < 512) {
            b = id & 3; h = (id >> 2) & 7; q0 = ((id >> 5) & 7) * 64;
            const int sp = id >> 8;
            Qp = amr_qk; Kp = vis_qk; Vp = vis_v;
            Lq = NN; LkT = MM; kv0 = sp * (MM / 2); nch = (MM / 2) / 64;
            mask = nullptr; norm = 0;
            Opf = po + (size_t)sp * BB * NN * DD;
            Lp  = pl + sp * BB * HH * NN;
        } else {
            const int j = id - 512;
            b = j & 3; h = (j >> 2) & 7; q0 = (j >> 5) * 64;
            Qp = vis_qk; Kp = amr_qk; Vp = amr_v;
            Lq = MM; LkT = NN; kv0 = 0; nch = NN / 64;
            mask = pad_mask; norm = 1;
            Oph = vis_att;
        }
    }

    const int tid  = threadIdx.x;
    const int w    = tid >> 5;
    const int lane = tid & 31;
    const int g    = lane >> 2;
    const int t    = lane & 3;
    const int m    = lane >> 3;
    const int r    = lane & 7;
    const int sr   = tid >> 1;              // Q staging row 0..63 (block-wide)
    const int scb  = (tid & 1) * 16;        // staging col (halves)
    const int wr   = 16 * w + (lane >> 1);  // this warp's own K/V staging row

    const uint32_t q_l = (uint32_t)(((m & 1) * 8 + r) * 80 + (m >> 1) * 16);
    const uint32_t k_l = (uint32_t)(((m >> 1) * 8 + r) * 80 + (m & 1) * 16);
    const uint32_t v_l = (uint32_t)(r * 80 + m * 16);
    const uint32_t onesb = (g == 0) ? 0x3C003C00u : 0u;   // B col 0 = ones

    __half (*QsW)[40]     = reinterpret_cast<__half(*)[40]>(SM);
    __half (*KbW)[64][40] = reinterpret_cast<__half(*)[64][40]>(SM + 5120);
    __half (*VbW)[64][40] = reinterpret_cast<__half(*)[64][40]>(SM + 15360);

    // Per-warp staging: each warp copies ONLY its own rows [16w,16w+16).
    auto stageKV = [&](int s, int kc) {
        const size_t base = ((size_t)b * LkT + kv0 + kc + wr) * 256 + h * 32 + scb;
        CP16(smem_u32(&KbW[s][wr][scb]),     &Kp[base]);
        CP16(smem_u32(&KbW[s][wr][scb + 8]), &Kp[base + 8]);
        CP16(smem_u32(&VbW[s][wr][scb]),     &Vp[base]);
        CP16(smem_u32(&VbW[s][wr][scb + 8]), &Vp[base + 8]);
    };

    // Prologue: Q (block-wide) + first KV chunk (per-warp), ONE group.
    {
        const size_t qb = ((size_t)b * Lq + q0 + sr) * 256 + h * 32 + scb;
        CP16(smem_u32(&QsW[sr][scb]),     &Qp[qb]);
        CP16(smem_u32(&QsW[sr][scb + 8]), &Qp[qb + 8]);
    }
    stageKV(0, 0);
    CP_COMMIT();

    uint32_t qa[4][2][4];          // [m-tile][kk][frag]
    float of[4][4][4];             // [m-tile][n-tile][frag] partial O
    float lf[4][4];                // [m-tile][frag]        partial l
    #pragma unroll
    for (int mt = 0; mt < 4; mt++) {
        #pragma unroll
        for (int nt = 0; nt < 4; nt++)
            #pragma unroll
            for (int i = 0; i < 4; i++) of[mt][nt][i] = 0.0f;
        #pragma unroll
        for (int i = 0; i < 4; i++) lf[mt][i] = 0.0f;
    }

    for (int c = 0; c < nch; c++) {
        // Prefetch next chunk (per-warp group), then drain chunk c's group.
        if (c + 1 < nch) { stageKV((c + 1) & 1, (c + 1) * 64); CP_COMMIT(); CP_WAIT(1); }
        else             { CP_WAIT(0); }
        const int s = c & 1;

        if (c == 0) {
            __syncthreads();   // all threads' Q (and own KV0) writes visible
            const uint32_t qb = qbase + q_l;
            #pragma unroll
            for (int mt = 0; mt < 4; mt++) {
                LDM4(qa[mt][0][0], qa[mt][0][1], qa[mt][0][2], qa[mt][0][3],
                     qb + mt * 1280);
                LDM4(qa[mt][1][0], qa[mt][1][1], qa[mt][1][2], qa[mt][1][3],
                     qb + mt * 1280 + 32);
            }
        }

        // ---- K frags for this warp's 16 keys (2 ldmatrix) ----
        uint32_t kf[2][4];
        {
            const uint32_t kb = kbase + s * KBUF + w * 1280 + k_l;
            LDM4(kf[0][0], kf[0][1], kf[0][2], kf[0][3], kb);
            LDM4(kf[1][0], kf[1][1], kf[1][2], kf[1][3], kb + 32);
        }

        // ---- Scores: 64 queries x 16 keys (pre-scaled by C2EXP) ----
        float sf[4][2][4];
        #pragma unroll
        for (int mt = 0; mt < 4; mt++) {
            #pragma unroll
            for (int nt = 0; nt < 2; nt++) {
                sf[mt][nt][0] = 0.0f; sf[mt][nt][1] = 0.0f;
                sf[mt][nt][2] = 0.0f; sf[mt][nt][3] = 0.0f;
            }
            #pragma unroll
            for (int kk = 0; kk < 2; kk++) {
                mma_f16(sf[mt][0], qa[mt][kk][0], qa[mt][kk][1],
                        qa[mt][kk][2], qa[mt][kk][3], kf[kk][0], kf[kk][1]);
                mma_f16(sf[mt][1], qa[mt][kk][0], qa[mt][kk][1],
                        qa[mt][kk][2], qa[mt][kk][3], kf[kk][2], kf[kk][3]);
            }
        }

        // ---- mask (direct LDG, L1-hot; dir2 only) + exp2 -> P A-frags ----
        int mb0 = 0, mb1 = 0, mb2 = 0, mb3 = 0;
        if (mask) {
            const int cb = b * LkT + kv0 + c * 64 + 16 * w + 2 * t;
            mb0 = mask[cb]; mb1 = mask[cb + 1]; mb2 = mask[cb + 8]; mb3 = mask[cb + 9];
        }
        uint32_t pa[4][4];
        #pragma unroll
        for (int mt = 0; mt < 4; mt++) {
            if (mask) {
                if (mb0) { sf[mt][0][0] = -3.0e38f; sf[mt][0][2] = -3.0e38f; }
                if (mb1) { sf[mt][0][1] = -3.0e38f; sf[mt][0][3] = -3.0e38f; }
                if (mb2) { sf[mt][1][0] = -3.0e38f; sf[mt][1][2] = -3.0e38f; }
                if (mb3) { sf[mt][1][1] = -3.0e38f; sf[mt][1][3] = -3.0e38f; }
            }
            pa[mt][0] = ex2_h2(pack_h2(sf[mt][0][0], sf[mt][0][1]));
            pa[mt][1] = ex2_h2(pack_h2(sf[mt][0][2], sf[mt][0][3]));
            pa[mt][2] = ex2_h2(pack_h2(sf[mt][1][0], sf[mt][1][1]));
            pa[mt][3] = ex2_h2(pack_h2(sf[mt][1][2], sf[mt][1][3]));
        }

        // ---- V frags (2 ldmatrix.trans) + PV + ones-l ----
        uint32_t vb0[4], vb1[4];
        {
            const uint32_t vb = vbase + s * KBUF + w * 1280 + v_l;
            LDM4T(vb0[0], vb0[1], vb0[2], vb0[3], vb);
            LDM4T(vb1[0], vb1[1], vb1[2], vb1[3], vb + 640);
        }
        #pragma unroll
        for (int mt = 0; mt < 4; mt++) {
            #pragma unroll
            for (int nt = 0; nt < 4; nt++)
                mma_f16(of[mt][nt], pa[mt][0], pa[mt][1], pa[mt][2], pa[mt][3],
                        vb0[nt], vb1[nt]);
            mma_f16(lf[mt], pa[mt][0], pa[mt][1], pa[mt][2], pa[mt][3],
                    onesb, onesb);
        }
    }
    __syncthreads();   // all warps done computing before overlaying reduce bufs

    // ---- cross-warp reduction (smem overlaid on dead Q/K/V buffers) ----
    #pragma unroll
    for (int mt = 0; mt < 4; mt++) {
        const int rlo = 16 * mt + g;
        #pragma unroll
        for (int nt = 0; nt < 4; nt++) {
            const int col = 8 * nt + 2 * t;
            *(float2*)&red[w][rlo][col]     = make_float2(of[mt][nt][0], of[mt][nt][1]);
            *(float2*)&red[w][rlo + 8][col] = make_float2(of[mt][nt][2], of[mt][nt][3]);
        }
        if (t == 0) {
            lred[w][rlo]     = lf[mt][0];
            lred[w][rlo + 8] = lf[mt][2];
        }
    }
    __syncthreads();

    // Each warp finalizes 16 rows; lane -> (row, col-half)
    const int rr = 16 * w + (lane >> 1);
    const int cc = (lane & 1) * 16;
    const float l_tot = lred[0][rr] + lred[1][rr] + lred[2][rr] + lred[3][rr];
    float oacc[16];
    #pragma unroll
    for (int c4 = 0; c4 < 4; c4++) {
        const float4 v = *(const float4*)&red[0][rr][cc + c4 * 4];
        oacc[c4 * 4 + 0] = v.x; oacc[c4 * 4 + 1] = v.y;
        oacc[c4 * 4 + 2] = v.z; oacc[c4 * 4 + 3] = v.w;
    }
    #pragma unroll
    for (int ww = 1; ww < 4; ww++)
        #pragma unroll
        for (int c4 = 0; c4 < 4; c4++) {
            const float4 v = *(const float4*)&red[ww][rr][cc + c4 * 4];
            oacc[c4 * 4 + 0] += v.x; oacc[c4 * 4 + 1] += v.y;
            oacc[c4 * 4 + 2] += v.z; oacc[c4 * 4 + 3] += v.w;
        }

    if (norm) {
        const float inv = 1.0f / l_tot;
        __half* dst = &Oph[((size_t)b * Lq + q0 + rr) * 256 + h * 32 + cc];
        #pragma unroll
        for (int c2 = 0; c2 < 8; c2++)
            *(half2*)&dst[c2 * 2] =
                __floats2half2_rn(oacc[c2 * 2] * inv, oacc[c2 * 2 + 1] * inv);
    } else {
        float* dst = &Opf[((size_t)b * Lq + q0 + rr) * 256 + h * 32 + cc];
        #pragma unroll
        for (int c4 = 0; c4 < 4; c4++) {
            float4 v;
            v.x = oacc[c4 * 4 + 0]; v.y = oacc[c4 * 4 + 1];
            v.z = oacc[c4 * 4 + 2]; v.w = oacc[c4 * 4 + 3];
            *(float4*)&dst[c4 * 4] = v;
        }
        if (cc == 0)
            Lp[((size_t)b * HH + h) * NN + q0 + rr] = l_tot;
    }
}

// ---------------------------------------------------------------------------
// Combine dir1 split partials: att = f16((O0+O1)/(l0+l1))
// ---------------------------------------------------------------------------
__global__ void combine2(const float* __restrict__ po,
                         const float* __restrict__ pl,
                         __half* __restrict__ out)
{
    const int i4 = (blockIdx.x * 256 + threadIdx.x) * 4;
    if (i4 >= BB * NN * DD) return;
    const int b = i4 / (NN * DD);
    const int rem = i4 - b * NN * DD;
    const int q = rem / DD;
    const float l = pl[((size_t)b * HH + ((rem - q * DD) >> 5)) * NN + q] +
                    pl[(size_t)BB * HH * NN +
                       ((size_t)b * HH + ((rem - q * DD) >> 5)) * NN + q];
    const float inv = 1.0f / l;
    const float4 o0 = *(const float4*)&po[i4];
    const float4 o1 = *(const float4*)&po[BB * NN * DD + i4];
    *(half2*)&out[i4]     = __floats2half2_rn((o0.x + o1.x) * inv, (o0.y + o1.y) * inv);
    *(half2*)&out[i4 + 2] = __floats2half2_rn((o0.z + o1.z) * inv, (o0.w + o1.w) * inv);
}

// ---------------------------------------------------------------------------
extern "C" void kernel_launch(void* const* d_in, const int* in_sizes, int n_in,
                              void* d_out, int out_size)
{
    const float* amr      = (const float*)d_in[0];
    const int*   pad_mask = (const int*)  d_in[1];
    const float* vis      = (const float*)d_in[2];
    const float* W_amr_qk = (const float*)d_in[3];
    const float* W_amr_v  = (const float*)d_in[4];
    const float* W_vis_qk = (const float*)d_in[5];
    const float* W_vis_v  = (const float*)d_in[6];
    const float* W_amr_out= (const float*)d_in[7];
    const float* b_amr_out= (const float*)d_in[8];
    const float* W_vis_out= (const float*)d_in[9];
    const float* b_vis_out= (const float*)d_in[10];

    float* out_amr = (float*)d_out;
    float* out_vis = out_amr + (size_t)BB * NN * DD;

    __half *amr_h, *vis_h, *Wt, *amr_qk, *amr_v, *vis_qk, *vis_v, *amr_att, *vis_att;
    float *po, *pl;
    cudaGetSymbolAddress((void**)&amr_h,   g_amr_h);
    cudaGetSymbolAddress((void**)&vis_h,   g_vis_h);
    cudaGetSymbolAddress((void**)&Wt,      g_Wt);
    cudaGetSymbolAddress((void**)&amr_qk,  g_amr_qk);
    cudaGetSymbolAddress((void**)&amr_v,   g_amr_v);
    cudaGetSymbolAddress((void**)&vis_qk,  g_vis_qk);
    cudaGetSymbolAddress((void**)&vis_v,   g_vis_v);
    cudaGetSymbolAddress((void**)&amr_att, g_amr_att);
    cudaGetSymbolAddress((void**)&vis_att, g_vis_att);
    cudaGetSymbolAddress((void**)&po,      g_po);
    cudaGetSymbolAddress((void**)&pl,      g_pl);

    prep_all<<<4992, 256>>>(amr, vis, W_amr_qk, W_amr_v, W_vis_qk, W_vis_v,
                            W_amr_out, W_vis_out, amr_h, vis_h, Wt);

    proj_all<<<dim3(4, 576), 128>>>(amr_h, vis_h, Wt, amr_qk, amr_v, vis_qk, vis_v);

    attn_all<<<2560, 128>>>(amr_qk, amr_v, vis_qk, vis_v, vis_att, po, pl, pad_mask);

    combine2<<<(BB*NN*DD) / 1024, 256>>>(po, pl, amr_att);

    epi_all<<<dim3(4, 288), 128>>>(amr_att, vis_att, Wt, b_amr_out, b_vis_out,
                                   amr, vis, out_amr, out_vis);
}